// round 1
// baseline (speedup 1.0000x reference)
#include <cuda_runtime.h>
#include <cuda_bf16.h>
#include <math_constants.h>

// Problem constants
#define NQ   65536          // 16*4096 query vectors
#define DIM  64
#define NK   8192           // codebook size
#define TQ   128            // queries per block (argmin kernel)
#define TK   128            // codes per k-tile

// Output layout (flattened fp32, reference return order)
#define ZQ_OFF   0
#define LOSS_OFF 4194304
#define ENC_OFF  4194305
#define CS_OFF   4259841
#define EA_OFF   4268033
#define W_OFF    4792321

typedef unsigned long long ull;

// ------------------------- scratch (device globals; no allocs) ------------
__device__ float  g_zn[(size_t)NQ * DIM];     // normalized z (16 MB)
__device__ float  g_w2[NK];                   // per-code squared norm
__device__ int    g_enc[NQ];                  // argmin indices
__device__ float  g_bins[NK];                 // histogram
__device__ float  g_es[(size_t)NK * DIM];     // embed_sum (2 MB)
__device__ double g_loss;                     // loss accumulator

// ------------------------- f32x2 helpers ----------------------------------
__device__ __forceinline__ void fma2(ull& d, ull a, ull b) {
    asm("fma.rn.f32x2 %0, %1, %2, %0;" : "+l"(d) : "l"(a), "l"(b));
}
__device__ __forceinline__ void unpack2(ull v, float& lo, float& hi) {
    asm("mov.b64 {%0, %1}, %2;" : "=f"(lo), "=f"(hi) : "l"(v));
}

// ------------------------- kernel 0: zero scratch --------------------------
__global__ void k_zero() {
    int idx = blockIdx.x * blockDim.x + threadIdx.x;
    if (idx < NK * DIM) g_es[idx] = 0.0f;
    int j = idx - NK * DIM;
    if (j >= 0 && j < NK) g_bins[j] = 0.0f;
    if (idx == 0) g_loss = 0.0;
}

// ------------------------- kernel 1: normalize z ---------------------------
// one warp per row; each lane handles a float2 (64 floats = 32 float2)
__global__ void k_normz(const float* __restrict__ Z) {
    int warp = (blockIdx.x * blockDim.x + threadIdx.x) >> 5;
    int lane = threadIdx.x & 31;
    if (warp >= NQ) return;
    float2 v = reinterpret_cast<const float2*>(Z)[(size_t)warp * 32 + lane];
    float ss = v.x * v.x + v.y * v.y;
    #pragma unroll
    for (int off = 16; off > 0; off >>= 1)
        ss += __shfl_xor_sync(0xffffffffu, ss, off);
    float inv = 1.0f / fmaxf(sqrtf(ss), 1e-12f);
    reinterpret_cast<float2*>(g_zn)[(size_t)warp * 32 + lane] =
        make_float2(v.x * inv, v.y * inv);
}

// ------------------------- kernel 2: w2 ------------------------------------
__global__ void k_w2(const float* __restrict__ W) {
    int warp = (blockIdx.x * blockDim.x + threadIdx.x) >> 5;
    int lane = threadIdx.x & 31;
    if (warp >= NK) return;
    float2 v = reinterpret_cast<const float2*>(W)[(size_t)warp * 32 + lane];
    float ss = v.x * v.x + v.y * v.y;
    #pragma unroll
    for (int off = 16; off > 0; off >>= 1)
        ss += __shfl_xor_sync(0xffffffffu, ss, off);
    if (lane == 0) g_w2[warp] = ss;
}

// ------------------------- kernel 3: argmin (f32x2 SGEMM-argmin) -----------
// Block: 256 threads = 16(tx over k) x 16(ty over q). Micro-tile 8q x 8k.
// smem: sZ duplicated pairs [64][128 float2] = 64KB, sW transposed [64][128] = 32KB, sw2 = 512B.
__global__ __launch_bounds__(256, 2)
void k_argmin(const float* __restrict__ W) {
    extern __shared__ float sm[];
    float* sZ  = sm;                      // 64 * 256 floats (duplicated pairs)
    float* sW  = sm + 64 * 256;           // 64 * 128 floats
    float* sw2 = sW + 64 * 128;           // 128 floats

    const int tid = threadIdx.x;
    const int tx = tid & 15;
    const int ty = tid >> 4;
    const int q0 = blockIdx.x * TQ;

    // Load Z tile, transposed + duplicated: sZ[d][2q]=sZ[d][2q+1]=zn[q][d]
    {
        const float4* Z4 = reinterpret_cast<const float4*>(g_zn) + (size_t)q0 * 16;
        float2* sZ2 = reinterpret_cast<float2*>(sZ);
        #pragma unroll
        for (int rep = 0; rep < 8; ++rep) {
            int idx = rep * 256 + tid;
            int c4 = idx >> 7, q = idx & 127;
            float4 v = Z4[(size_t)q * 16 + c4];
            sZ2[(c4 * 4 + 0) * 128 + q] = make_float2(v.x, v.x);
            sZ2[(c4 * 4 + 1) * 128 + q] = make_float2(v.y, v.y);
            sZ2[(c4 * 4 + 2) * 128 + q] = make_float2(v.z, v.z);
            sZ2[(c4 * 4 + 3) * 128 + q] = make_float2(v.w, v.w);
        }
    }

    float minv[8];
    int   mini[8];
    #pragma unroll
    for (int i = 0; i < 8; ++i) { minv[i] = CUDART_INF_F; mini[i] = 0; }

    for (int kt = 0; kt < NK / TK; ++kt) {
        __syncthreads();  // previous tile compute done (and sZ visible on kt==0)
        // Load W tile transposed: sW[d][k] = W[kt*128+k][d]; conflict-free stores
        {
            const float4* W4 = reinterpret_cast<const float4*>(W) + (size_t)kt * TK * 16;
            #pragma unroll
            for (int rep = 0; rep < 8; ++rep) {
                int idx = rep * 256 + tid;
                int c4 = idx >> 7, k = idx & 127;
                float4 v = W4[(size_t)k * 16 + c4];
                sW[(c4 * 4 + 0) * 128 + k] = v.x;
                sW[(c4 * 4 + 1) * 128 + k] = v.y;
                sW[(c4 * 4 + 2) * 128 + k] = v.z;
                sW[(c4 * 4 + 3) * 128 + k] = v.w;
            }
            if (tid < 128) sw2[tid] = g_w2[kt * 128 + tid];
        }
        __syncthreads();

        ull acc[32];
        #pragma unroll
        for (int i = 0; i < 32; ++i) acc[i] = 0ull;  // (0.f, 0.f)

        #pragma unroll 8
        for (int d = 0; d < 64; ++d) {
            const ull* bp = reinterpret_cast<const ull*>(&sW[d * 128 + tx * 8]);
            ull b0 = bp[0], b1 = bp[1], b2 = bp[2], b3 = bp[3];
            const ull* ap = reinterpret_cast<const ull*>(&sZ[d * 256 + ty * 16]);
            #pragma unroll
            for (int qi = 0; qi < 8; ++qi) {
                ull a = ap[qi];
                fma2(acc[qi * 4 + 0], a, b0);
                fma2(acc[qi * 4 + 1], a, b1);
                fma2(acc[qi * 4 + 2], a, b2);
                fma2(acc[qi * 4 + 3], a, b3);
            }
        }

        // epilogue: score = w2[k] - 2*dot ; ascending scan keeps lowest index on ties
        int kbase = kt * 128 + tx * 8;
        #pragma unroll
        for (int qi = 0; qi < 8; ++qi) {
            #pragma unroll
            for (int kp = 0; kp < 4; ++kp) {
                float lo, hi;
                unpack2(acc[qi * 4 + kp], lo, hi);
                float s0 = fmaf(-2.0f, lo, sw2[tx * 8 + kp * 2]);
                float s1 = fmaf(-2.0f, hi, sw2[tx * 8 + kp * 2 + 1]);
                if (s0 < minv[qi]) { minv[qi] = s0; mini[qi] = kbase + kp * 2; }
                if (s1 < minv[qi]) { minv[qi] = s1; mini[qi] = kbase + kp * 2 + 1; }
            }
        }
    }

    // reduce across the 16 tx-threads (same half-warp, width 16)
    #pragma unroll
    for (int off = 8; off > 0; off >>= 1) {
        #pragma unroll
        for (int qi = 0; qi < 8; ++qi) {
            float ov = __shfl_down_sync(0xffffffffu, minv[qi], off, 16);
            int   oi = __shfl_down_sync(0xffffffffu, mini[qi], off, 16);
            if (ov < minv[qi] || (ov == minv[qi] && oi < mini[qi])) {
                minv[qi] = ov; mini[qi] = oi;
            }
        }
    }
    if (tx == 0) {
        #pragma unroll
        for (int qi = 0; qi < 8; ++qi)
            g_enc[q0 + ty * 8 + qi] = mini[qi];
    }
}

// ------------------------- kernel 4: scatter / z_q / loss ------------------
// one warp per query row
__global__ void k_scatter(const float* __restrict__ W, float* __restrict__ out) {
    int warp = (blockIdx.x * blockDim.x + threadIdx.x) >> 5;
    int lane = threadIdx.x & 31;
    if (warp >= NQ) return;
    int e = g_enc[warp];

    float2 wv = reinterpret_cast<const float2*>(W)[(size_t)e * 32 + lane];
    float2 zv = reinterpret_cast<const float2*>(g_zn)[(size_t)warp * 32 + lane];
    float d0 = wv.x - zv.x, d1 = wv.y - zv.y;
    // z_q = z + (z_q - z), computed exactly as the reference does
    reinterpret_cast<float2*>(out + ZQ_OFF)[(size_t)warp * 32 + lane] =
        make_float2(zv.x + d0, zv.y + d1);

    atomicAdd(&g_es[(size_t)e * 64 + 2 * lane],     zv.x);
    atomicAdd(&g_es[(size_t)e * 64 + 2 * lane + 1], zv.y);

    float part = d0 * d0 + d1 * d1;
    #pragma unroll
    for (int off = 16; off > 0; off >>= 1)
        part += __shfl_xor_sync(0xffffffffu, part, off);
    if (lane == 0) {
        atomicAdd(&g_bins[e], 1.0f);
        atomicAdd(&g_loss, (double)part);
        out[ENC_OFF + warp] = (float)e;
    }
}

// ------------------------- kernel 5: per-code EMA updates ------------------
// one warp per code row
__global__ void k_update(const float* __restrict__ W,
                         const float* __restrict__ CS,
                         const float* __restrict__ EA,
                         float* __restrict__ out) {
    int warp = (blockIdx.x * blockDim.x + threadIdx.x) >> 5;
    int lane = threadIdx.x & 31;
    if (blockIdx.x == 0 && threadIdx.x == 0) {
        out[LOSS_OFF] = (float)(0.25 * (g_loss / (double)((size_t)NQ * DIM)));
    }
    if (warp >= NK) return;
    int k = warp;

    float b = g_bins[k];
    float2 es = reinterpret_cast<const float2*>(g_es)[(size_t)k * 32 + lane];
    float2 ea = reinterpret_cast<const float2*>(EA)[(size_t)k * 32 + lane];

    // new_embed_avg (offset is odd -> scalar stores)
    out[EA_OFF + (size_t)k * 64 + 2 * lane]     = ea.x * 0.99f + 0.01f * es.x;
    out[EA_OFF + (size_t)k * 64 + 2 * lane + 1] = ea.y * 0.99f + 0.01f * es.y;

    float bc = (b == 0.0f) ? 1.0f : b;
    float vx = es.x / bc, vy = es.y / bc;
    float ss = vx * vx + vy * vy;
    #pragma unroll
    for (int off = 16; off > 0; off >>= 1)
        ss += __shfl_xor_sync(0xffffffffu, ss, off);
    float inv = 1.0f / fmaxf(sqrtf(ss), 1e-12f);

    float2 wv = reinterpret_cast<const float2*>(W)[(size_t)k * 32 + lane];
    float enx = (b == 0.0f) ? wv.x : vx * inv;
    float eny = (b == 0.0f) ? wv.y : vy * inv;

    float nwx = wv.x * 0.99f + 0.01f * enx;
    float nwy = wv.y * 0.99f + 0.01f * eny;
    float ss2 = nwx * nwx + nwy * nwy;
    #pragma unroll
    for (int off = 16; off > 0; off >>= 1)
        ss2 += __shfl_xor_sync(0xffffffffu, ss2, off);
    float inv2 = 1.0f / fmaxf(sqrtf(ss2), 1e-12f);

    out[W_OFF + (size_t)k * 64 + 2 * lane]     = nwx * inv2;
    out[W_OFF + (size_t)k * 64 + 2 * lane + 1] = nwy * inv2;

    if (lane == 0) out[CS_OFF + k] = CS[k] * 0.99f + 0.01f * b;
}

// ------------------------- launch -------------------------------------------
extern "C" void kernel_launch(void* const* d_in, const int* in_sizes, int n_in,
                              void* d_out, int out_size) {
    const float* z  = (const float*)d_in[0];
    const float* w  = (const float*)d_in[1];
    const float* cs = (const float*)d_in[2];
    const float* ea = (const float*)d_in[3];
    float* out = (float*)d_out;

    const int smem_bytes = (64 * 256 + 64 * 128 + 128) * sizeof(float);  // 98816
    cudaFuncSetAttribute(k_argmin, cudaFuncAttributeMaxDynamicSharedMemorySize,
                         smem_bytes);

    k_zero<<<(NK * DIM + NK + 255) / 256, 256>>>();
    k_normz<<<NQ / 8, 256>>>(z);
    k_w2<<<NK / 8, 256>>>(w);
    k_argmin<<<NQ / TQ, 256, smem_bytes>>>(w);
    k_scatter<<<NQ / 8, 256>>>(w, out);
    k_update<<<NK / 8, 256>>>(w, cs, ea, out);
}

// round 2
// speedup vs baseline: 1.0943x; 1.0943x over previous
#include <cuda_runtime.h>
#include <cuda_bf16.h>
#include <math_constants.h>

// Problem constants
#define NQ   65536          // 16*4096 query vectors
#define DIM  64
#define NK   8192           // codebook size
#define TQ   128            // queries per block (argmin kernel)
#define TK   128            // codes per k-tile

// Output layout (flattened fp32, reference return order)
#define ZQ_OFF   0
#define LOSS_OFF 4194304
#define ENC_OFF  4194305
#define CS_OFF   4259841
#define EA_OFF   4268033
#define W_OFF    4792321

typedef unsigned long long ull;

// ------------------------- scratch (device globals; no allocs) ------------
__device__ float  g_zn[(size_t)NQ * DIM];     // normalized z (16 MB)
__device__ float  g_w2[NK];                   // per-code squared norm
__device__ int    g_enc[NQ];                  // argmin indices
__device__ float  g_bins[NK];                 // histogram
__device__ float  g_es[(size_t)NK * DIM];     // embed_sum (2 MB)
__device__ double g_loss;                     // loss accumulator

// ------------------------- f32x2 helpers ----------------------------------
__device__ __forceinline__ void fma2(ull& d, ull a, ull b) {
    asm("fma.rn.f32x2 %0, %1, %2, %0;" : "+l"(d) : "l"(a), "l"(b));
}
__device__ __forceinline__ void unpack2(ull v, float& lo, float& hi) {
    asm("mov.b64 {%0, %1}, %2;" : "=f"(lo), "=f"(hi) : "l"(v));
}

// ------------------------- kernel 0: zero scratch --------------------------
__global__ void k_zero() {
    int idx = blockIdx.x * blockDim.x + threadIdx.x;
    if (idx < NK * DIM) g_es[idx] = 0.0f;
    int j = idx - NK * DIM;
    if (j >= 0 && j < NK) g_bins[j] = 0.0f;
    if (idx == 0) g_loss = 0.0;
}

// ------------------------- kernel 1: normalize z ---------------------------
__global__ void k_normz(const float* __restrict__ Z) {
    int warp = (blockIdx.x * blockDim.x + threadIdx.x) >> 5;
    int lane = threadIdx.x & 31;
    if (warp >= NQ) return;
    float2 v = reinterpret_cast<const float2*>(Z)[(size_t)warp * 32 + lane];
    float ss = v.x * v.x + v.y * v.y;
    #pragma unroll
    for (int off = 16; off > 0; off >>= 1)
        ss += __shfl_xor_sync(0xffffffffu, ss, off);
    float inv = 1.0f / fmaxf(sqrtf(ss), 1e-12f);
    reinterpret_cast<float2*>(g_zn)[(size_t)warp * 32 + lane] =
        make_float2(v.x * inv, v.y * inv);
}

// ------------------------- kernel 2: w2 ------------------------------------
__global__ void k_w2(const float* __restrict__ W) {
    int warp = (blockIdx.x * blockDim.x + threadIdx.x) >> 5;
    int lane = threadIdx.x & 31;
    if (warp >= NK) return;
    float2 v = reinterpret_cast<const float2*>(W)[(size_t)warp * 32 + lane];
    float ss = v.x * v.x + v.y * v.y;
    #pragma unroll
    for (int off = 16; off > 0; off >>= 1)
        ss += __shfl_xor_sync(0xffffffffu, ss, off);
    if (lane == 0) g_w2[warp] = ss;
}

// ------------------------- kernel 3: argmin (f32x2 SGEMM-argmin) -----------
// Block: 256 threads = 16(tx over k) x 16(ty over q). Micro-tile 8q x 8k.
// k mapping per thread: pair j in 0..3 covers codes  j*32 + tx*2 + {0,1}
//  -> warp's 16 tx lanes read 128 CONTIGUOUS bytes per B LDS.64 (1 wavefront).
// smem: sZ duplicated pairs [64][128 float2] = 64KB, sW transposed [64][128] = 32KB.
__global__ __launch_bounds__(256, 2)
void k_argmin(const float* __restrict__ W) {
    extern __shared__ float sm[];
    float* sZ  = sm;                      // 64 * 256 floats (duplicated pairs)
    float* sW  = sm + 64 * 256;           // 64 * 128 floats
    float* sw2 = sW + 64 * 128;           // 128 floats

    const int tid = threadIdx.x;
    const int tx = tid & 15;
    const int ty = tid >> 4;
    const int q0 = blockIdx.x * TQ;

    // Load Z tile, transposed + duplicated: sZ[d][2q]=sZ[d][2q+1]=zn[q][d]
    {
        const float4* Z4 = reinterpret_cast<const float4*>(g_zn) + (size_t)q0 * 16;
        float2* sZ2 = reinterpret_cast<float2*>(sZ);
        #pragma unroll
        for (int rep = 0; rep < 8; ++rep) {
            int idx = rep * 256 + tid;
            int c4 = idx >> 7, q = idx & 127;
            float4 v = Z4[(size_t)q * 16 + c4];
            sZ2[(c4 * 4 + 0) * 128 + q] = make_float2(v.x, v.x);
            sZ2[(c4 * 4 + 1) * 128 + q] = make_float2(v.y, v.y);
            sZ2[(c4 * 4 + 2) * 128 + q] = make_float2(v.z, v.z);
            sZ2[(c4 * 4 + 3) * 128 + q] = make_float2(v.w, v.w);
        }
    }

    float minv[8];
    int   mini[8];
    #pragma unroll
    for (int i = 0; i < 8; ++i) { minv[i] = CUDART_INF_F; mini[i] = 0; }

    for (int kt = 0; kt < NK / TK; ++kt) {
        __syncthreads();  // previous tile compute done (and sZ visible on kt==0)
        // Load W tile transposed: sW[d][k] = W[kt*128+k][d]
        {
            const float4* W4 = reinterpret_cast<const float4*>(W) + (size_t)kt * TK * 16;
            #pragma unroll
            for (int rep = 0; rep < 8; ++rep) {
                int idx = rep * 256 + tid;
                int c4 = idx >> 7, k = idx & 127;
                float4 v = W4[(size_t)k * 16 + c4];
                sW[(c4 * 4 + 0) * 128 + k] = v.x;
                sW[(c4 * 4 + 1) * 128 + k] = v.y;
                sW[(c4 * 4 + 2) * 128 + k] = v.z;
                sW[(c4 * 4 + 3) * 128 + k] = v.w;
            }
            if (tid < 128) sw2[tid] = g_w2[kt * 128 + tid];
        }
        __syncthreads();

        ull acc[32];
        #pragma unroll
        for (int i = 0; i < 32; ++i) acc[i] = 0ull;  // (0.f, 0.f)

        #pragma unroll 8
        for (int d = 0; d < 64; ++d) {
            // B pairs: pair index j*16 + tx  ->  codes j*32 + tx*2 + {0,1}
            const ull* bp = reinterpret_cast<const ull*>(&sW[d * 128]);
            ull b0 = bp[0 * 16 + tx];
            ull b1 = bp[1 * 16 + tx];
            ull b2 = bp[2 * 16 + tx];
            ull b3 = bp[3 * 16 + tx];
            const ull* ap = reinterpret_cast<const ull*>(sZ) + d * 128 + ty * 8;
            #pragma unroll
            for (int qi = 0; qi < 8; ++qi) {
                ull a = ap[qi];
                fma2(acc[qi * 4 + 0], a, b0);
                fma2(acc[qi * 4 + 1], a, b1);
                fma2(acc[qi * 4 + 2], a, b2);
                fma2(acc[qi * 4 + 3], a, b3);
            }
        }

        // epilogue: score = w2[k] - 2*dot ; ascending j keeps ascending k,
        // strict < keeps the lowest index on ties.
        int kbase = kt * 128 + tx * 2;
        #pragma unroll
        for (int qi = 0; qi < 8; ++qi) {
            #pragma unroll
            for (int j = 0; j < 4; ++j) {
                float lo, hi;
                unpack2(acc[qi * 4 + j], lo, hi);
                float s0 = fmaf(-2.0f, lo, sw2[j * 32 + tx * 2]);
                float s1 = fmaf(-2.0f, hi, sw2[j * 32 + tx * 2 + 1]);
                int k0 = kbase + j * 32;
                if (s0 < minv[qi]) { minv[qi] = s0; mini[qi] = k0; }
                if (s1 < minv[qi]) { minv[qi] = s1; mini[qi] = k0 + 1; }
            }
        }
    }

    // reduce across the 16 tx-threads (same half-warp, width 16)
    #pragma unroll
    for (int off = 8; off > 0; off >>= 1) {
        #pragma unroll
        for (int qi = 0; qi < 8; ++qi) {
            float ov = __shfl_down_sync(0xffffffffu, minv[qi], off, 16);
            int   oi = __shfl_down_sync(0xffffffffu, mini[qi], off, 16);
            if (ov < minv[qi] || (ov == minv[qi] && oi < mini[qi])) {
                minv[qi] = ov; mini[qi] = oi;
            }
        }
    }
    if (tx == 0) {
        #pragma unroll
        for (int qi = 0; qi < 8; ++qi)
            g_enc[q0 + ty * 8 + qi] = mini[qi];
    }
}

// ------------------------- kernel 4: scatter / z_q / loss ------------------
__global__ void k_scatter(const float* __restrict__ W, float* __restrict__ out) {
    int warp = (blockIdx.x * blockDim.x + threadIdx.x) >> 5;
    int lane = threadIdx.x & 31;
    if (warp >= NQ) return;
    int e = g_enc[warp];

    float2 wv = reinterpret_cast<const float2*>(W)[(size_t)e * 32 + lane];
    float2 zv = reinterpret_cast<const float2*>(g_zn)[(size_t)warp * 32 + lane];
    float d0 = wv.x - zv.x, d1 = wv.y - zv.y;
    reinterpret_cast<float2*>(out + ZQ_OFF)[(size_t)warp * 32 + lane] =
        make_float2(zv.x + d0, zv.y + d1);

    atomicAdd(&g_es[(size_t)e * 64 + 2 * lane],     zv.x);
    atomicAdd(&g_es[(size_t)e * 64 + 2 * lane + 1], zv.y);

    float part = d0 * d0 + d1 * d1;
    #pragma unroll
    for (int off = 16; off > 0; off >>= 1)
        part += __shfl_xor_sync(0xffffffffu, part, off);
    if (lane == 0) {
        atomicAdd(&g_bins[e], 1.0f);
        atomicAdd(&g_loss, (double)part);
        out[ENC_OFF + warp] = (float)e;
    }
}

// ------------------------- kernel 5: per-code EMA updates ------------------
__global__ void k_update(const float* __restrict__ W,
                         const float* __restrict__ CS,
                         const float* __restrict__ EA,
                         float* __restrict__ out) {
    int warp = (blockIdx.x * blockDim.x + threadIdx.x) >> 5;
    int lane = threadIdx.x & 31;
    if (blockIdx.x == 0 && threadIdx.x == 0) {
        out[LOSS_OFF] = (float)(0.25 * (g_loss / (double)((size_t)NQ * DIM)));
    }
    if (warp >= NK) return;
    int k = warp;

    float b = g_bins[k];
    float2 es = reinterpret_cast<const float2*>(g_es)[(size_t)k * 32 + lane];
    float2 ea = reinterpret_cast<const float2*>(EA)[(size_t)k * 32 + lane];

    out[EA_OFF + (size_t)k * 64 + 2 * lane]     = ea.x * 0.99f + 0.01f * es.x;
    out[EA_OFF + (size_t)k * 64 + 2 * lane + 1] = ea.y * 0.99f + 0.01f * es.y;

    float bc = (b == 0.0f) ? 1.0f : b;
    float vx = es.x / bc, vy = es.y / bc;
    float ss = vx * vx + vy * vy;
    #pragma unroll
    for (int off = 16; off > 0; off >>= 1)
        ss += __shfl_xor_sync(0xffffffffu, ss, off);
    float inv = 1.0f / fmaxf(sqrtf(ss), 1e-12f);

    float2 wv = reinterpret_cast<const float2*>(W)[(size_t)k * 32 + lane];
    float enx = (b == 0.0f) ? wv.x : vx * inv;
    float eny = (b == 0.0f) ? wv.y : vy * inv;

    float nwx = wv.x * 0.99f + 0.01f * enx;
    float nwy = wv.y * 0.99f + 0.01f * eny;
    float ss2 = nwx * nwx + nwy * nwy;
    #pragma unroll
    for (int off = 16; off > 0; off >>= 1)
        ss2 += __shfl_xor_sync(0xffffffffu, ss2, off);
    float inv2 = 1.0f / fmaxf(sqrtf(ss2), 1e-12f);

    out[W_OFF + (size_t)k * 64 + 2 * lane]     = nwx * inv2;
    out[W_OFF + (size_t)k * 64 + 2 * lane + 1] = nwy * inv2;

    if (lane == 0) out[CS_OFF + k] = CS[k] * 0.99f + 0.01f * b;
}

// ------------------------- launch -------------------------------------------
extern "C" void kernel_launch(void* const* d_in, const int* in_sizes, int n_in,
                              void* d_out, int out_size) {
    const float* z  = (const float*)d_in[0];
    const float* w  = (const float*)d_in[1];
    const float* cs = (const float*)d_in[2];
    const float* ea = (const float*)d_in[3];
    float* out = (float*)d_out;

    const int smem_bytes = (64 * 256 + 64 * 128 + 128) * sizeof(float);  // 98816
    cudaFuncSetAttribute(k_argmin, cudaFuncAttributeMaxDynamicSharedMemorySize,
                         smem_bytes);

    k_zero<<<(NK * DIM + NK + 255) / 256, 256>>>();
    k_normz<<<NQ / 8, 256>>>(z);
    k_w2<<<NK / 8, 256>>>(w);
    k_argmin<<<NQ / TQ, 256, smem_bytes>>>(w);
    k_scatter<<<NQ / 8, 256>>>(w, out);
    k_update<<<NK / 8, 256>>>(w, cs, ea, out);
}